// round 4
// baseline (speedup 1.0000x reference)
#include <cuda_runtime.h>
#include <math_constants.h>

// ---------------------------------------------------------------------------
// MultiTaskLossWrapper: two Cox losses + two pair-rank losses + scalar combine
// Inputs: 0 hazard3d f32[B], 1 hazard1d f32[B], 2 survtime f32[B],
//         3 censor f32[B], 4 vars_ f32[4], 5 beta1, 6 beta2,
//         7 age i32[B], 8 grade i32[B].  Output: f32[1]
//
// Cox via sort: bucket survtime (B buckets), exact within-bucket rank,
// suffix-sum of exp(h) in sorted order -> masked logsumexp is a lookup.
// ---------------------------------------------------------------------------

#define BMAX 4096
#define K1_T 1024
#define NE 4                 // BMAX / K1_T
#define NPAIR 128
#define LOWTILE 256
#define HITILE 128

__constant__ float c_risk_table[9] = {1.0f, 1.0f, 0.91f, 1.12f, 1.71f,
                                      2.41f, 3.27f, 5.18f, 8.44f};

// device-global scratch (no allocations; smem atomics only affect scatter
// order within a bucket, never numeric results -> fully deterministic)
__device__ float2 g_cox;               // (sum censor*(h3-lse3), same for h1)
__device__ int    g_cnt[4];            // compacted list sizes
__device__ int    g_meta[4][BMAX];     // (orig_idx<<4) | decade_bucket
__device__ float  g_hlist[4][BMAX];    // hazard3d
__device__ float4 g_pair_part[NPAIR];

__device__ __forceinline__ float warpSum(float v) {
#pragma unroll
    for (int o = 16; o; o >>= 1) v += __shfl_xor_sync(0xffffffffu, v, o);
    return v;
}

// ===========================================================================
// K1: single block. exp, sort-rank, suffix sums, cox total, list compaction.
// ===========================================================================
__global__ void __launch_bounds__(K1_T)
prep_kernel(const float* __restrict__ h3, const float* __restrict__ h1,
            const float* __restrict__ surv, const float* __restrict__ censor,
            const int* __restrict__ age, const int* __restrict__ grade, int B) {
    extern __shared__ int smdyn[];
    int*      s_hist = smdyn;                       // [B]
    int*      s_base = s_hist + B;                  // [B]
    unsigned* s_key  = (unsigned*)(s_base + B);     // [B]
    int*      s_slot = (int*)(s_key + B);           // [B]
    float2*   s_val  = (float2*)(s_slot + B);       // [B]

    __shared__ float  s_red[64];
    __shared__ float2 s_wsum[32];
    __shared__ int    s_wtot[32];
    __shared__ int    s_wb[4][32];
    __shared__ int    s_lb[4];

    const int tid = threadIdx.x;
    const int w = tid >> 5;
    const int lane = tid & 31;

    for (int p = tid; p < B; p += K1_T) s_hist[p] = 0;
    if (tid < 4) s_lb[tid] = 0;
    __syncthreads();

    // ---- phase A: load everything, exp, bucket, histogram ---------------
    float e3r[NE], e1r[NE], h3r[NE], h1r[NE], cenr[NE];
    int bktr[NE], er[NE], ager[NE], grr[NE];
    unsigned keyr[NE];
    bool vr[NE];
#pragma unroll
    for (int k = 0; k < NE; k++) {
        int e = k * K1_T + tid;
        er[k] = e;
        bool v = (e < B);
        vr[k] = v;
        e3r[k] = e1r[k] = h3r[k] = h1r[k] = cenr[k] = 0.0f;
        bktr[k] = 0; keyr[k] = 0; ager[k] = -1; grr[k] = -1;
        if (v) {
            float s = surv[e];
            h3r[k] = h3[e];
            h1r[k] = h1[e];
            cenr[k] = censor[e];
            e3r[k] = __expf(h3r[k]);
            e1r[k] = __expf(h1r[k]);
            keyr[k] = __float_as_uint(s);   // surv >= 0: bits are monotone
            int b = (int)(s * (float)B);
            if (b > B - 1) b = B - 1;
            if (b < 0) b = 0;
            bktr[k] = b;
            s_key[e] = keyr[k];
            atomicAdd(&s_hist[b], 1);
            ager[k] = age[e];
            grr[k] = grade[e];
        }
    }
    __syncthreads();

    // ---- phase B: exclusive prefix scan of s_hist -> s_base --------------
    int hh[NE];
    int lsum = 0;
#pragma unroll
    for (int k = 0; k < NE; k++) {
        int p = tid * NE + k;
        hh[k] = (p < B) ? s_hist[p] : 0;
        lsum += hh[k];
    }
    int x = lsum;
#pragma unroll
    for (int o = 1; o < 32; o <<= 1) {
        int y = __shfl_up_sync(0xffffffffu, x, o);
        if (lane >= o) x += y;
    }
    if (lane == 31) s_wtot[w] = x;
    __syncthreads();
    if (w == 0) {
        int t = s_wtot[lane];
        int xx = t;
#pragma unroll
        for (int o = 1; o < 32; o <<= 1) {
            int y = __shfl_up_sync(0xffffffffu, xx, o);
            if (lane >= o) xx += y;
        }
        s_wtot[lane] = xx - t;   // exclusive warp base
    }
    __syncthreads();
    int run = s_wtot[w] + (x - lsum);
#pragma unroll
    for (int k = 0; k < NE; k++) {
        int p = tid * NE + k;
        if (p < B) s_base[p] = run;
        run += hh[k];
    }
    __syncthreads();

    // ---- phase C: scatter element ids into bucket segments ---------------
#pragma unroll
    for (int k = 0; k < NE; k++)
        if (vr[k]) {
            int pos = atomicAdd(&s_base[bktr[k]], 1);  // s_base becomes inclusive
            s_slot[pos] = er[k];
        }
    __syncthreads();

    // ---- phase D: exact ranks, write sorted (e3,e1) ----------------------
    int rankr[NE];
#pragma unroll
    for (int k = 0; k < NE; k++) {
        rankr[k] = 0;
        if (vr[k]) {
            int b = bktr[k];
            int cnt = s_hist[b];
            int st = s_base[b] - cnt;     // reconstruct exclusive base
            int lt = 0, eq = 0;
            unsigned mykey = keyr[k];
            int me = er[k];
            for (int j = 0; j < cnt; j++) {
                int oe = s_slot[st + j];
                unsigned ok = s_key[oe];
                lt += (ok < mykey) ? 1 : 0;
                eq += (ok == mykey && oe < me) ? 1 : 0;
            }
            rankr[k] = st + lt;            // first position with key >= mine
            s_val[st + lt + eq] = make_float2(e3r[k], e1r[k]);
        }
    }
    __syncthreads();

    // ---- phase E: suffix-inclusive scan of s_val (float2) ----------------
    float2 a[NE];
    float sx = 0.0f, sy = 0.0f;
#pragma unroll
    for (int k = 0; k < NE; k++) {
        int p = tid * NE + k;
        a[k] = (p < B) ? s_val[p] : make_float2(0.0f, 0.0f);
        sx += a[k].x;
        sy += a[k].y;
    }
    float tx = sx, ty = sy;
#pragma unroll
    for (int o = 1; o < 32; o <<= 1) {
        float yx = __shfl_down_sync(0xffffffffu, tx, o);
        float yy = __shfl_down_sync(0xffffffffu, ty, o);
        if (lane + o < 32) { tx += yx; ty += yy; }
    }
    if (lane == 0) s_wsum[w] = make_float2(tx, ty);  // warp total
    __syncthreads();
    if (w == 0) {
        float wx = s_wsum[lane].x, wy = s_wsum[lane].y;
        float ix = wx, iy = wy;
#pragma unroll
        for (int o = 1; o < 32; o <<= 1) {
            float yx = __shfl_down_sync(0xffffffffu, ix, o);
            float yy = __shfl_down_sync(0xffffffffu, iy, o);
            if (lane + o < 32) { ix += yx; iy += yy; }
        }
        s_wsum[lane] = make_float2(ix - wx, iy - wy);  // right-exclusive warp base
    }
    __syncthreads();
    float accx = s_wsum[w].x + (tx - sx);   // sum over threads strictly right
    float accy = s_wsum[w].y + (ty - sy);
#pragma unroll
    for (int k = NE - 1; k >= 0; k--) {
        int p = tid * NE + k;
        accx += a[k].x;
        accy += a[k].y;
        if (p < B) s_val[p] = make_float2(accx, accy);
    }
    __syncthreads();

    // ---- phase F: cox contributions + block reduce -----------------------
    float c3 = 0.0f, c1 = 0.0f;
#pragma unroll
    for (int k = 0; k < NE; k++)
        if (vr[k] && cenr[k] != 0.0f) {
            float2 sfx = s_val[rankr[k]];
            c3 += cenr[k] * (h3r[k] - __logf(sfx.x));
            c1 += cenr[k] * (h1r[k] - __logf(sfx.y));
        }
    c3 = warpSum(c3);
    c1 = warpSum(c1);
    if (lane == 0) { s_red[w] = c3; s_red[32 + w] = c1; }
    __syncthreads();
    if (w == 0) {
        float vA = warpSum(s_red[lane]);
        if (lane == 0) s_red[0] = vA;
    }
    if (w == 1) {
        float vB = warpSum(s_red[32 + lane]);
        if (lane == 0) s_red[32] = vB;
    }
    __syncthreads();
    if (tid == 0) g_cox = make_float2(s_red[0], s_red[32]);

    // ---- phase G: deterministic list compaction (ballot + scan) ----------
#pragma unroll
    for (int k = 0; k < NE; k++) {
        bool valid = vr[k];
        int a_ = ager[k], g_ = grr[k];
        bool g0  = (g_ == 0);
        bool g12 = (g_ == 1) || (g_ == 2);
        int db = a_ / 10; if (db > 8) db = 8; if (db < 0) db = 0;
        int meta = (er[k] << 4) | db;
        bool pred[4];
        pred[0] = valid && g0  && (a_ < 40);
        pred[1] = valid && g0  && (a_ >= 40);
        pred[2] = valid && g12 && (a_ < 65);
        pred[3] = valid && g12 && (a_ >= 65);
        unsigned mk[4];
#pragma unroll
        for (int l = 0; l < 4; l++) {
            mk[l] = __ballot_sync(0xffffffffu, pred[l]);
            if (lane == 0) s_wb[l][w] = __popc(mk[l]);
        }
        __syncthreads();
        if (w < 4) {
            int l = w;
            int c = s_wb[l][lane];
            int xx = c;
#pragma unroll
            for (int o = 1; o < 32; o <<= 1) {
                int y = __shfl_up_sync(0xffffffffu, xx, o);
                if (lane >= o) xx += y;
            }
            int excl = xx - c;
            int base2 = s_lb[l];
            s_wb[l][lane] = base2 + excl;
            if (lane == 31) s_lb[l] = base2 + excl + c;
        }
        __syncthreads();
#pragma unroll
        for (int l = 0; l < 4; l++) {
            if (pred[l]) {
                int pos = s_wb[l][w] + __popc(mk[l] & ((1u << lane) - 1u));
                g_meta[l][pos]  = meta;
                g_hlist[l][pos] = h3r[k];
            }
        }
        __syncthreads();
    }
    if (tid < 4) g_cnt[tid] = s_lb[tid];
}

// ===========================================================================
// K2: pair-rank losses over compacted lists (tiled, grid-stride)
// ===========================================================================
__global__ void __launch_bounds__(256)
pair_kernel(const float* __restrict__ beta1p, const float* __restrict__ beta2p) {
    __shared__ float tabL[81], tabH[81];
    __shared__ int   smeta[HITILE];
    __shared__ float shh[HITILE];
    __shared__ float pr[4][8];

    const int tid = threadIdx.x;
    const int w = tid >> 5;
    const int lane = tid & 31;

    if (tid < 81) {
        float b1 = *beta1p, b2 = *beta2p;
        int bi = tid / 9, bj = tid % 9;
        float d = (c_risk_table[bj] - c_risk_table[bi]) * 0.125f;
        tabL[tid] = d / (1.0f + __expf(-b1 * d));
        tabH[tid] = d / (1.0f + __expf(-b2 * d));
    }

    const int nLL = g_cnt[0], nHL = g_cnt[1], nLH = g_cnt[2], nHH = g_cnt[3];
    const int tlL = (nLL + LOWTILE - 1) / LOWTILE;
    const int thL = (nHL + HITILE - 1) / HITILE;
    const int tlH = (nLH + LOWTILE - 1) / LOWTILE;
    const int thH = (nHH + HITILE - 1) / HITILE;
    const int TL = tlL * thL;
    const int T  = TL + tlH * thH;

    float accS0 = 0.0f, accC0 = 0.0f, accS1 = 0.0f, accC1 = 0.0f;
    __syncthreads();

    for (int t = blockIdx.x; t < T; t += gridDim.x) {
        int prob, lt, ht, nLow, nHigh, llist, hlist;
        if (t < TL) { prob = 0; lt = t / thL; ht = t - lt * thL;
                      nLow = nLL; nHigh = nHL; llist = 0; hlist = 1; }
        else        { int tt = t - TL; prob = 1; lt = tt / thH; ht = tt - lt * thH;
                      nLow = nLH; nHigh = nHH; llist = 2; hlist = 3; }

        int j0 = ht * HITILE;
        int hcount = nHigh - j0;
        if (hcount > HITILE) hcount = HITILE;

        __syncthreads();
        if (tid < hcount) {
            smeta[tid] = g_meta[hlist][j0 + tid];
            shh[tid]   = g_hlist[hlist][j0 + tid];
        }
        __syncthreads();

        int li = lt * LOWTILE + tid;
        if (li < nLow) {
            int mi = g_meta[llist][li];
            int idxi = mi >> 4;
            const float* tab = prob ? tabH : tabL;
            int rowoff = (mi & 15) * 9;
            float hi = g_hlist[llist][li];
            float s = 0.0f, c = 0.0f;
            for (int jj = 0; jj < hcount; jj++) {
                int mj = smeta[jj];
                if ((mj >> 4) > idxi) {
                    float alpha = tab[rowoff + (mj & 15)];
                    float xv = alpha * (hi - shh[jj]);
                    float e = __expf(-fabsf(xv));
                    s += fmaxf(xv, 0.0f) + __logf(1.0f + e);
                    c += 1.0f;
                }
            }
            if (prob == 0) { accS0 += s; accC0 += c; }
            else           { accS1 += s; accC1 += c; }
        }
    }

    accS0 = warpSum(accS0); accC0 = warpSum(accC0);
    accS1 = warpSum(accS1); accC1 = warpSum(accC1);
    if (lane == 0) {
        pr[0][w] = accS0; pr[1][w] = accC0;
        pr[2][w] = accS1; pr[3][w] = accC1;
    }
    __syncthreads();
    if (tid == 0) {
        float a = 0.f, b = 0.f, c = 0.f, d = 0.f;
#pragma unroll
        for (int k = 0; k < 8; k++) {
            a += pr[0][k]; b += pr[1][k]; c += pr[2][k]; d += pr[3][k];
        }
        g_pair_part[blockIdx.x] = make_float4(a, b, c, d);
    }
}

// ===========================================================================
// K3: final reduce + combine
// ===========================================================================
__global__ void __launch_bounds__(128)
final_kernel(const float* __restrict__ vars, float* __restrict__ out, int B) {
    __shared__ float red[4][4];
    const int tid = threadIdx.x;
    float a2 = 0.f, a3 = 0.f, a4 = 0.f, a5 = 0.f;
    for (int i = tid; i < NPAIR; i += 128) {
        float4 p = g_pair_part[i];
        a2 += p.x; a3 += p.y; a4 += p.z; a5 += p.w;
    }
    a2 = warpSum(a2); a3 = warpSum(a3); a4 = warpSum(a4); a5 = warpSum(a5);
    const int lane = tid & 31, w = tid >> 5;
    if (lane == 0) {
        red[0][w] = a2; red[1][w] = a3; red[2][w] = a4; red[3][w] = a5;
    }
    __syncthreads();
    if (tid == 0) {
        float s2 = 0.f, s3 = 0.f, s4 = 0.f, s5 = 0.f;
#pragma unroll
        for (int k = 0; k < 4; k++) {
            s2 += red[0][k]; s3 += red[1][k]; s4 += red[2][k]; s5 += red[3][k];
        }
        float2 cox = g_cox;
        float invB = 1.0f / (float)B;
        float loss3d = -cox.x * invB;
        float loss1d = -cox.y * invB;
        float lgg = (s3 > 0.5f) ? (s2 / s3) : 0.0f;
        float hgg = (s5 > 0.5f) ? (s4 / s5) : 0.0f;
        float losscli = lgg + hgg;
        float v0 = vars[0], v2 = vars[2], v3 = vars[3];
        out[0] = 0.5f * loss3d / (v0 * v0) + logf(v0)
               + 0.5f * loss1d / (v2 * v2) + logf(v2)
               + 0.5f * losscli / (v3 * v3) + logf(v3);
    }
}

extern "C" void kernel_launch(void* const* d_in, const int* in_sizes, int n_in,
                              void* d_out, int out_size) {
    const float* h3     = (const float*)d_in[0];
    const float* h1     = (const float*)d_in[1];
    const float* surv   = (const float*)d_in[2];
    const float* censor = (const float*)d_in[3];
    const float* vars   = (const float*)d_in[4];
    const float* beta1  = (const float*)d_in[5];
    const float* beta2  = (const float*)d_in[6];
    const int*   age    = (const int*)d_in[7];
    const int*   grade  = (const int*)d_in[8];
    int B = in_sizes[0];

    size_t smem = (size_t)B * (4 * sizeof(int) + sizeof(float2));  // 24B bytes
    cudaFuncSetAttribute(prep_kernel, cudaFuncAttributeMaxDynamicSharedMemorySize,
                         (int)smem);

    prep_kernel<<<1, K1_T, smem>>>(h3, h1, surv, censor, age, grade, B);
    pair_kernel<<<NPAIR, 256>>>(beta1, beta2);
    final_kernel<<<1, 128>>>(vars, (float*)d_out, B);
}